// round 13
// baseline (speedup 1.0000x reference)
#include <cuda_runtime.h>
#include <cstdint>

// TorchWrithe: writhe of all non-adjacent segment pairs per frame.
// B=128, N=300, SEG_LEN=1 -> S=44253 pairs, out (B,S) f32.
//
// Scalar-math version (f32x2 packing measured counterproductive: it halves
// per-warp ILP and issue efficiency drops 86%->63%, cancelling the slot win).
// Keeps all measured wins: precomputed (i,j) table (no divergent inversion),
// 3-cross direct-dot basis (c0=-A, c1=B-C, c2=A-C, c3=-B with A=v0xw,
// B=v0xu, C=wxu), branchless deg-7 asin, linear smem slab with float4 fill.

#define N_FRAMES_C 128
#define N_ATOMS_C  300
#define S_PAIRS_C  44253
#define BLOCK_T 128
#define F_TILE 4
#define FLOATS_PER_FRAME (N_ATOMS_C * 3)          // 900
#define SLAB_FLOATS (F_TILE * FLOATS_PER_FRAME)   // 3600
#define SLAB_VEC4 (SLAB_FLOATS / 4)               // 900

__device__ int g_ij[S_PAIRS_C];                   // packed (i<<16)|j

__device__ __forceinline__ int fcum(int i) {
    return 297 * i - (i * (i - 1)) / 2;
}

__global__ void init_idx_kernel() {
    int s = blockIdx.x * 256 + threadIdx.x;
    if (s >= S_PAIRS_C) return;
    float disc = 354025.0f - 8.0f * (float)s;
    int i = (int)((595.0f - sqrtf(disc)) * 0.5f);
    if (i < 0) i = 0;
    if (i > 296) i = 296;
    while (i > 0 && fcum(i) > s) --i;
    while (fcum(i + 1) <= s) ++i;
    int j = i + 2 + (s - fcum(i));
    g_ij[s] = (i << 16) | j;
}

struct V3 { float x, y, z; };

__device__ __forceinline__ V3 vsub(V3 a, V3 b) { return {a.x-b.x, a.y-b.y, a.z-b.z}; }
__device__ __forceinline__ V3 vcross(V3 a, V3 b) {
    return { a.y*b.z - a.z*b.y,
             a.z*b.x - a.x*b.z,
             a.x*b.y - a.y*b.x };
}
__device__ __forceinline__ float vdot(V3 a, V3 b) {
    return fmaf(a.x, b.x, fmaf(a.y, b.y, a.z * b.z));
}

__device__ __forceinline__ float sqrt_approx(float x) {
    float r; asm("sqrt.approx.f32 %0,%1;" : "=f"(r) : "f"(x)); return r;
}

// Branchless asin via A&S 4.4.46 (deg-7): asin(a) = pi/2 - sqrt(1-a)*P(a),
// a in [0,1], |err|<=2e-8. Magnitude result >= 0, so sign restore is an OR of
// t's sign bit. |t| slightly > 1 from rounding clamps to +-pi/2 via fmaxf.
__device__ __forceinline__ float fast_asin(float t) {
    float a = fabsf(t);
    float m = fmaxf(1.0f - a, 0.0f);
    float s = sqrt_approx(m);
    float p =            0.0012624911f;      // negated A&S coefficients
    p = fmaf(p, a,      -0.0066700901f);
    p = fmaf(p, a,       0.0170881256f);
    p = fmaf(p, a,      -0.0308918810f);
    p = fmaf(p, a,       0.0501743046f);
    p = fmaf(p, a,      -0.0889789874f);
    p = fmaf(p, a,       0.2145988016f);
    p = fmaf(p, a,      -1.5707963050f);
    float r = fmaf(s, p, 1.5707963267948966f);   // >= 0
    return __int_as_float(__float_as_int(r)
                        | (__float_as_int(t) & 0x80000000u));
}

__global__ __launch_bounds__(BLOCK_T, 10)
void writhe_kernel(const float* __restrict__ xyz, float* __restrict__ out) {
    __shared__ float sm[SLAB_FLOATS];            // 14400 B, linear slab

    const int b0 = blockIdx.y * F_TILE;
    {
        const float4* __restrict__ src4 =
            (const float4*)(xyz + (size_t)b0 * FLOATS_PER_FRAME);
        float4* dst4 = (float4*)sm;
        #pragma unroll
        for (int k = 0; k < 8; ++k) {
            int t = threadIdx.x + k * BLOCK_T;
            if (t < SLAB_VEC4) dst4[t] = src4[t];
        }
    }
    __syncthreads();

    const int s = blockIdx.x * BLOCK_T + threadIdx.x;
    if (s >= S_PAIRS_C) return;

    const int ij = g_ij[s];                      // one L2-resident LDG
    const int i = ij >> 16;
    const int j = ij & 0xFFFF;

    const float* __restrict__ bi = sm + 3 * i;   // atoms i, i+1
    const float* __restrict__ bj = sm + 3 * j;   // atoms j, j+1
    float* __restrict__ op = out + (size_t)b0 * S_PAIRS_C + s;

    const float K = 0.15915494309189535f;        // 1/(2*pi)

    #pragma unroll 2
    for (int f = 0; f < F_TILE; ++f) {
        const float* ai = bi + f * FLOATS_PER_FRAME;
        const float* aj = bj + f * FLOATS_PER_FRAME;
        V3 p0 = { ai[0], ai[1], ai[2] };
        V3 p1 = { ai[3], ai[4], ai[5] };
        V3 p2 = { aj[0], aj[1], aj[2] };
        V3 p3 = { aj[3], aj[4], aj[5] };

        // Unnormalized basis (normalization cancels everywhere).
        V3 w  = vsub(p1, p0);
        V3 u  = vsub(p3, p2);
        V3 v0 = vsub(p2, p0);

        V3 A = vcross(v0, w);
        V3 B = vcross(v0, u);
        V3 C = vcross(w,  u);

        V3 c1 = vsub(B, C);                      // c1 = B - C
        V3 cm = vsub(A, C);                      // c2 = A - C

        float aa  = vdot(A, A);                  // n0
        float bb  = vdot(B, B);                  // n3
        float n1  = vdot(c1, c1);
        float n2  = vdot(cm, cm);
        float e01 = vdot(A, c1);                 // d01 = -e01
        float d12 = vdot(c1, cm);
        float e23 = vdot(cm, B);                 // d23 = -e23
        float ab  = vdot(A, B);                  // d30
        float au  = vdot(A, u);                  // sign = sign(-au)

        float t0 = e01 * -rsqrtf(aa * n1);       // neg folds d01 = -e01
        float t1 = d12 *  rsqrtf(n1 * n2);
        float t2 = e23 * -rsqrtf(n2 * bb);       // neg folds d23 = -e23
        float t3 = ab  *  rsqrtf(bb * aa);

        float omega = fast_asin(t0) + fast_asin(t1)
                    + fast_asin(t2) + fast_asin(t3);

        // sign(dot(c0, v2)) = sign(-au); fold 1/(2pi).
        float g = (au < 0.0f) ? K : ((au > 0.0f) ? -K : 0.0f);

        op[(size_t)f * S_PAIRS_C] = omega * g;
    }
}

extern "C" void kernel_launch(void* const* d_in, const int* in_sizes, int n_in,
                              void* d_out, int out_size) {
    const float* xyz = (const float*)d_in[0];
    float* out = (float*)d_out;
    init_idx_kernel<<<(S_PAIRS_C + 255) / 256, 256>>>();
    dim3 grid((S_PAIRS_C + BLOCK_T - 1) / BLOCK_T, N_FRAMES_C / F_TILE);
    writhe_kernel<<<grid, BLOCK_T>>>(xyz, out);
}

// round 14
// speedup vs baseline: 1.0046x; 1.0046x over previous
#include <cuda_runtime.h>
#include <cstdint>

// TorchWrithe: writhe of all non-adjacent segment pairs per frame.
// B=128, N=300, SEG_LEN=1 -> S=44253 pairs, out (B,S) f32.
//
// Packed f32x2 geometry (two frames per instruction), PAIRS=1 per block tile
// to minimize register pressure -> 10 blocks/SM. s->(i,j) inverted inline,
// branchless (f32 sqrt exact at row boundaries; single predicated +-1 fixup).
// Basis: w=p1-p0, u=p3-p2, v0=p2-p0; A=v0xw, B=v0xu, C=wxu;
//   c0=-A, c1=B-C, c2=A-C, c3=-B  (3 crosses, direct dots, no cancellation).

#define N_FRAMES_C 128
#define N_ATOMS_C  300
#define S_PAIRS_C  44253
#define BLOCK_T 128
#define F_TILE 2
#define FLOATS_PER_FRAME (N_ATOMS_C * 3)          // 900
#define VEC4_PER_FRAME (FLOATS_PER_FRAME / 4)     // 225

__device__ __forceinline__ int fcum(int i) {
    return 297 * i - (i * (i - 1)) / 2;
}

// ---------- packed f32x2 primitives ----------
struct P2 { unsigned long long v; };

__device__ __forceinline__ P2 pk(float lo, float hi) {
    P2 r; asm("mov.b64 %0,{%1,%2};" : "=l"(r.v) : "f"(lo), "f"(hi)); return r;
}
__device__ __forceinline__ void up(P2 p, float& lo, float& hi) {
    asm("mov.b64 {%0,%1},%2;" : "=f"(lo), "=f"(hi) : "l"(p.v));
}
__device__ __forceinline__ P2 fma2(P2 a, P2 b, P2 c) {
    P2 r; asm("fma.rn.f32x2 %0,%1,%2,%3;" : "=l"(r.v) : "l"(a.v), "l"(b.v), "l"(c.v));
    return r;
}
__device__ __forceinline__ P2 mul2(P2 a, P2 b) {
    P2 r; asm("mul.rn.f32x2 %0,%1,%2;" : "=l"(r.v) : "l"(a.v), "l"(b.v));
    return r;
}
__device__ __forceinline__ P2 add2(P2 a, P2 b) {
    P2 r; asm("add.rn.f32x2 %0,%1,%2;" : "=l"(r.v) : "l"(a.v), "l"(b.v));
    return r;
}
__device__ __forceinline__ P2 c2(float x) { return pk(x, x); }

template <int OFF>
__device__ __forceinline__ P2 lds64(uint32_t base) {
    P2 r; asm("ld.shared.b64 %0,[%1+%2];" : "=l"(r.v) : "r"(base), "n"(OFF));
    return r;
}

struct V3P { P2 x, y, z; };

__device__ __forceinline__ P2 sub2_(P2 a, P2 b, P2 NEG1) { return fma2(b, NEG1, a); }

__device__ __forceinline__ V3P vsub2(V3P a, V3P b, P2 NEG1) {
    return { sub2_(a.x, b.x, NEG1), sub2_(a.y, b.y, NEG1), sub2_(a.z, b.z, NEG1) };
}
__device__ __forceinline__ V3P vcross2(V3P a, V3P b, P2 NEG1) {
    V3P r;
    r.x = sub2_(mul2(a.y, b.z), mul2(a.z, b.y), NEG1);
    r.y = sub2_(mul2(a.z, b.x), mul2(a.x, b.z), NEG1);
    r.z = sub2_(mul2(a.x, b.y), mul2(a.y, b.x), NEG1);
    return r;
}
__device__ __forceinline__ P2 vdot2(V3P a, V3P b) {
    return fma2(a.z, b.z, fma2(a.y, b.y, mul2(a.x, b.x)));
}

__device__ __forceinline__ float sqrt_approx(float x) {
    float r; asm("sqrt.approx.f32 %0,%1;" : "=f"(r) : "f"(x)); return r;
}

// Packed asin via A&S 4.4.46 (deg-7): asin(a) = pi/2 - sqrt(1-a)*P(a), a in
// [0,1], |err|<=2e-8. Magnitude >= 0, so sign restore is an OR of t's sign
// bits. |t| slightly > 1 from rounding clamps to +-pi/2 via fmaxf(1-a, 0).
__device__ __forceinline__ P2 asin2(P2 t, P2 ONE, P2 NEG1, P2 HALFPI) {
    P2 a; a.v = t.v & 0x7FFFFFFF7FFFFFFFull;      // |t| both lanes
    P2 m = fma2(a, NEG1, ONE);                    // 1 - |t|
    float ml, mh; up(m, ml, mh);
    float sl = sqrt_approx(fmaxf(ml, 0.0f));      // sqrt(1-|t|)
    float sh = sqrt_approx(fmaxf(mh, 0.0f));
    P2 s = pk(sl, sh);
    P2 p = c2( 0.0012624911f);                    // negated A&S coefficients
    p = fma2(p, a, c2(-0.0066700901f));
    p = fma2(p, a, c2( 0.0170881256f));
    p = fma2(p, a, c2(-0.0308918810f));
    p = fma2(p, a, c2( 0.0501743046f));
    p = fma2(p, a, c2(-0.0889789874f));
    p = fma2(p, a, c2( 0.2145988016f));
    p = fma2(p, a, c2(-1.5707963050f));
    P2 r = fma2(s, p, HALFPI);                    // >= 0
    r.v |= (t.v & 0x8000000080000000ull);         // copysign (r >= 0)
    return r;
}

__global__ __launch_bounds__(BLOCK_T, 10)
void writhe_kernel(const float* __restrict__ xyz, float* __restrict__ out) {
    // Interleaved slab: sm2[k] = {frameA[k], frameB[k]}.
    __shared__ float2 sm2[FLOATS_PER_FRAME];      // 7200 B

    const int b0 = blockIdx.y * F_TILE;
    {
        const float4* __restrict__ fA =
            (const float4*)(xyz + (size_t)b0 * FLOATS_PER_FRAME);
        const float4* __restrict__ fB =
            (const float4*)(xyz + (size_t)(b0 + 1) * FLOATS_PER_FRAME);
        #pragma unroll
        for (int k = 0; k < 2; ++k) {
            int kq = threadIdx.x + k * BLOCK_T;
            if (kq < VEC4_PER_FRAME) {
                float4 a = fA[kq];
                float4 c = fB[kq];
                float2* d = &sm2[4 * kq];
                d[0] = make_float2(a.x, c.x);
                d[1] = make_float2(a.y, c.y);
                d[2] = make_float2(a.z, c.z);
                d[3] = make_float2(a.w, c.w);
            }
        }
    }
    __syncthreads();

    const int s = blockIdx.x * BLOCK_T + threadIdx.x;
    if (s >= S_PAIRS_C) return;

    // Closed-form s -> (i, j), branchless single-step fixup.
    // sqrtf is exact at row boundaries ((595-2i)^2 < 2^24); interior error
    // << 1 step, so one predicated +-1 correction suffices.
    float r = sqrtf(354025.0f - 8.0f * (float)s);
    int i = (int)((595.0f - r) * 0.5f);
    i = min(max(i, 0), 296);
    i += (fcum(i + 1) <= s);
    i -= (fcum(i) > s);
    const int j = (s - fcum(i)) + i + 2;

    const uint32_t smbase = (uint32_t)__cvta_generic_to_shared(sm2);
    const uint32_t oi = smbase + 24u * (uint32_t)i;     // 3*i float2 (8B each)
    const uint32_t oj = smbase + 24u * (uint32_t)j;

    const P2 ONE    = c2(1.0f);
    const P2 NEG1   = c2(-1.0f);
    const P2 HALFPI = c2(1.5707963267948966f);
    const float K = 0.15915494309189535f;

    // Packed coords: lane-lo = frame b0, lane-hi = frame b0+1.
    V3P p0 = { lds64< 0>(oi), lds64< 8>(oi), lds64<16>(oi) };
    V3P p1 = { lds64<24>(oi), lds64<32>(oi), lds64<40>(oi) };
    V3P p2 = { lds64< 0>(oj), lds64< 8>(oj), lds64<16>(oj) };
    V3P p3 = { lds64<24>(oj), lds64<32>(oj), lds64<40>(oj) };

    V3P w  = vsub2(p1, p0, NEG1);
    V3P u  = vsub2(p3, p2, NEG1);
    V3P v0 = vsub2(p2, p0, NEG1);

    V3P A = vcross2(v0, w, NEG1);
    V3P B = vcross2(v0, u, NEG1);
    V3P C = vcross2(w,  u, NEG1);

    V3P c1 = vsub2(B, C, NEG1);            // c1 = B - C
    V3P cm = vsub2(A, C, NEG1);            // c2 = A - C

    // Direct dot products (no cancellation-prone combos).
    P2 aa  = vdot2(A, A);                  // n0
    P2 bb  = vdot2(B, B);                  // n3
    P2 n1  = vdot2(c1, c1);
    P2 n2  = vdot2(cm, cm);
    P2 e01 = vdot2(A, c1);                 // d01 = -e01
    P2 d12 = vdot2(c1, cm);
    P2 e23 = vdot2(cm, B);                 // d23 = -e23
    P2 ab  = vdot2(A, B);                  // d30
    P2 au  = vdot2(A, u);                  // sign = sign(-au)

    P2 q01 = mul2(aa, n1);
    P2 q12 = mul2(n1, n2);
    P2 q23 = mul2(n2, bb);
    P2 q30 = mul2(bb, aa);
    float ql, qh;
    up(q01, ql, qh); P2 r01 = pk(-rsqrtf(ql), -rsqrtf(qh));  // neg folds d01
    up(q12, ql, qh); P2 r12 = pk( rsqrtf(ql),  rsqrtf(qh));
    up(q23, ql, qh); P2 r23 = pk(-rsqrtf(ql), -rsqrtf(qh));  // neg folds d23
    up(q30, ql, qh); P2 r30 = pk( rsqrtf(ql),  rsqrtf(qh));

    P2 t0 = mul2(e01, r01);
    P2 t1 = mul2(d12, r12);
    P2 t2 = mul2(e23, r23);
    P2 t3 = mul2(ab,  r30);

    P2 omega = add2(add2(asin2(t0, ONE, NEG1, HALFPI),
                         asin2(t1, ONE, NEG1, HALFPI)),
                    add2(asin2(t2, ONE, NEG1, HALFPI),
                         asin2(t3, ONE, NEG1, HALFPI)));

    // sign(dot(c0, v2)) = sign(-au); fold 1/(2pi).
    float aul, auh; up(au, aul, auh);
    float gl = (aul < 0.0f) ? K : ((aul > 0.0f) ? -K : 0.0f);
    float gh = (auh < 0.0f) ? K : ((auh > 0.0f) ? -K : 0.0f);
    P2 res = mul2(omega, pk(gl, gh));

    float rl, rh; up(res, rl, rh);
    float* __restrict__ op = out + (size_t)b0 * S_PAIRS_C + s;
    op[0] = rl;
    op[S_PAIRS_C] = rh;
}

extern "C" void kernel_launch(void* const* d_in, const int* in_sizes, int n_in,
                              void* d_out, int out_size) {
    const float* xyz = (const float*)d_in[0];
    float* out = (float*)d_out;
    dim3 grid((S_PAIRS_C + BLOCK_T - 1) / BLOCK_T, N_FRAMES_C / F_TILE);
    writhe_kernel<<<grid, BLOCK_T>>>(xyz, out);
}

// round 15
// speedup vs baseline: 1.1151x; 1.1100x over previous
#include <cuda_runtime.h>
#include <cstdint>

// TorchWrithe: writhe of all non-adjacent segment pairs per frame.
// B=128, N=300, SEG_LEN=1 -> S=44253 pairs, out (B,S) f32.
//
// Measured-best configuration: packed f32x2 geometry (2 frames/instruction),
// PAIRS=2 per block (amortization sweet spot: PAIRS=4 -> 43.3us, PAIRS=2 ->
// 37.6us, PAIRS=1 -> 41.7us), interleaved LDS.64 smem slab, 3-cross
// direct-dot basis, deg-7 branchless asin. The s->(i,j) map is inverted
// inline and branchlessly (no init kernel: saves ~1.5us/replay; validated
// bit-identical to the table version in R14).

#define N_FRAMES_C 128
#define N_ATOMS_C  300
#define S_PAIRS_C  44253
#define BLOCK_T 128
#define F_TILE 4
#define PAIRS (F_TILE / 2)                        // 2
#define FLOATS_PER_FRAME (N_ATOMS_C * 3)          // 900
#define VEC4_PER_FRAME (FLOATS_PER_FRAME / 4)     // 225

__device__ __forceinline__ int fcum(int i) {
    return 297 * i - (i * (i - 1)) / 2;
}

// ---------- packed f32x2 primitives ----------
struct P2 { unsigned long long v; };

__device__ __forceinline__ P2 pk(float lo, float hi) {
    P2 r; asm("mov.b64 %0,{%1,%2};" : "=l"(r.v) : "f"(lo), "f"(hi)); return r;
}
__device__ __forceinline__ void up(P2 p, float& lo, float& hi) {
    asm("mov.b64 {%0,%1},%2;" : "=f"(lo), "=f"(hi) : "l"(p.v));
}
__device__ __forceinline__ P2 fma2(P2 a, P2 b, P2 c) {
    P2 r; asm("fma.rn.f32x2 %0,%1,%2,%3;" : "=l"(r.v) : "l"(a.v), "l"(b.v), "l"(c.v));
    return r;
}
__device__ __forceinline__ P2 mul2(P2 a, P2 b) {
    P2 r; asm("mul.rn.f32x2 %0,%1,%2;" : "=l"(r.v) : "l"(a.v), "l"(b.v));
    return r;
}
__device__ __forceinline__ P2 add2(P2 a, P2 b) {
    P2 r; asm("add.rn.f32x2 %0,%1,%2;" : "=l"(r.v) : "l"(a.v), "l"(b.v));
    return r;
}
__device__ __forceinline__ P2 c2(float x) { return pk(x, x); }

template <int OFF>
__device__ __forceinline__ P2 lds64(uint32_t base) {
    P2 r; asm("ld.shared.b64 %0,[%1+%2];" : "=l"(r.v) : "r"(base), "n"(OFF));
    return r;
}

struct V3P { P2 x, y, z; };

__device__ __forceinline__ P2 sub2_(P2 a, P2 b, P2 NEG1) { return fma2(b, NEG1, a); }

__device__ __forceinline__ V3P vsub2(V3P a, V3P b, P2 NEG1) {
    return { sub2_(a.x, b.x, NEG1), sub2_(a.y, b.y, NEG1), sub2_(a.z, b.z, NEG1) };
}
__device__ __forceinline__ V3P vcross2(V3P a, V3P b, P2 NEG1) {
    V3P r;
    r.x = sub2_(mul2(a.y, b.z), mul2(a.z, b.y), NEG1);
    r.y = sub2_(mul2(a.z, b.x), mul2(a.x, b.z), NEG1);
    r.z = sub2_(mul2(a.x, b.y), mul2(a.y, b.x), NEG1);
    return r;
}
__device__ __forceinline__ P2 vdot2(V3P a, V3P b) {
    return fma2(a.z, b.z, fma2(a.y, b.y, mul2(a.x, b.x)));
}

__device__ __forceinline__ float sqrt_approx(float x) {
    float r; asm("sqrt.approx.f32 %0,%1;" : "=f"(r) : "f"(x)); return r;
}

// Packed asin via A&S 4.4.46 (deg-7): asin(a) = pi/2 - sqrt(1-a)*P(a), a in
// [0,1], |err|<=2e-8. Magnitude >= 0, so sign restore is an OR of t's sign
// bits. |t| slightly > 1 from rounding clamps to +-pi/2 via fmaxf(1-a, 0).
__device__ __forceinline__ P2 asin2(P2 t, P2 ONE, P2 NEG1, P2 HALFPI) {
    P2 a; a.v = t.v & 0x7FFFFFFF7FFFFFFFull;      // |t| both lanes
    P2 m = fma2(a, NEG1, ONE);                    // 1 - |t|
    float ml, mh; up(m, ml, mh);
    float sl = sqrt_approx(fmaxf(ml, 0.0f));      // sqrt(1-|t|)
    float sh = sqrt_approx(fmaxf(mh, 0.0f));
    P2 s = pk(sl, sh);
    P2 p = c2( 0.0012624911f);                    // negated A&S coefficients
    p = fma2(p, a, c2(-0.0066700901f));
    p = fma2(p, a, c2( 0.0170881256f));
    p = fma2(p, a, c2(-0.0308918810f));
    p = fma2(p, a, c2( 0.0501743046f));
    p = fma2(p, a, c2(-0.0889789874f));
    p = fma2(p, a, c2( 0.2145988016f));
    p = fma2(p, a, c2(-1.5707963050f));
    P2 r = fma2(s, p, HALFPI);                    // >= 0
    r.v |= (t.v & 0x8000000080000000ull);         // copysign (r >= 0)
    return r;
}

__global__ __launch_bounds__(BLOCK_T, 8)
void writhe_kernel(const float* __restrict__ xyz, float* __restrict__ out) {
    // Interleaved slab: sm2[pg*900 + k] = {frame(2pg)[k], frame(2pg+1)[k]}.
    __shared__ float2 sm2[PAIRS * FLOATS_PER_FRAME];   // 14400 B

    const int b0 = blockIdx.y * F_TILE;
    #pragma unroll
    for (int pg = 0; pg < PAIRS; ++pg) {
        const float4* __restrict__ fA =
            (const float4*)(xyz + (size_t)(b0 + 2 * pg) * FLOATS_PER_FRAME);
        const float4* __restrict__ fB =
            (const float4*)(xyz + (size_t)(b0 + 2 * pg + 1) * FLOATS_PER_FRAME);
        #pragma unroll
        for (int k = 0; k < 2; ++k) {
            int kq = threadIdx.x + k * BLOCK_T;
            if (kq < VEC4_PER_FRAME) {
                float4 a = fA[kq];
                float4 c = fB[kq];
                float2* d = &sm2[pg * FLOATS_PER_FRAME + 4 * kq];
                d[0] = make_float2(a.x, c.x);
                d[1] = make_float2(a.y, c.y);
                d[2] = make_float2(a.z, c.z);
                d[3] = make_float2(a.w, c.w);
            }
        }
    }
    __syncthreads();

    const int s = blockIdx.x * BLOCK_T + threadIdx.x;
    if (s >= S_PAIRS_C) return;

    // Closed-form s -> (i, j), branchless single-step fixup (bit-identical to
    // the table version; sqrt boundary values < 2^24 so approx + fixup is safe).
    float rr = sqrt_approx(354025.0f - 8.0f * (float)s);
    int i = (int)((595.0f - rr) * 0.5f);
    i = min(max(i, 0), 296);
    i += (fcum(i + 1) <= s);
    i -= (fcum(i) > s);
    const int j = (s - fcum(i)) + i + 2;

    const uint32_t smbase = (uint32_t)__cvta_generic_to_shared(sm2);
    const uint32_t oi0 = smbase + 24u * (uint32_t)i;    // 3*i float2 (8B each)
    const uint32_t oj0 = smbase + 24u * (uint32_t)j;

    float* __restrict__ op = out + (size_t)b0 * S_PAIRS_C + s;

    const P2 ONE    = c2(1.0f);
    const P2 NEG1   = c2(-1.0f);
    const P2 HALFPI = c2(1.5707963267948966f);
    const float K = 0.15915494309189535f;

    #pragma unroll
    for (int pg = 0; pg < PAIRS; ++pg) {
        const uint32_t oi = oi0 + pg * FLOATS_PER_FRAME * 8;
        const uint32_t oj = oj0 + pg * FLOATS_PER_FRAME * 8;

        // Packed coords: lane-lo = frame 2pg, lane-hi = frame 2pg+1.
        V3P p0 = { lds64< 0>(oi), lds64< 8>(oi), lds64<16>(oi) };
        V3P p1 = { lds64<24>(oi), lds64<32>(oi), lds64<40>(oi) };
        V3P p2 = { lds64< 0>(oj), lds64< 8>(oj), lds64<16>(oj) };
        V3P p3 = { lds64<24>(oj), lds64<32>(oj), lds64<40>(oj) };

        V3P w  = vsub2(p1, p0, NEG1);
        V3P u  = vsub2(p3, p2, NEG1);
        V3P v0 = vsub2(p2, p0, NEG1);

        V3P A = vcross2(v0, w, NEG1);
        V3P B = vcross2(v0, u, NEG1);
        V3P C = vcross2(w,  u, NEG1);

        V3P c1 = vsub2(B, C, NEG1);            // c1 = B - C
        V3P cm = vsub2(A, C, NEG1);            // c2 = A - C

        // Direct dot products (no cancellation-prone combos).
        P2 aa  = vdot2(A, A);                  // n0
        P2 bb  = vdot2(B, B);                  // n3
        P2 n1  = vdot2(c1, c1);
        P2 n2  = vdot2(cm, cm);
        P2 e01 = vdot2(A, c1);                 // d01 = -e01
        P2 d12 = vdot2(c1, cm);
        P2 e23 = vdot2(cm, B);                 // d23 = -e23
        P2 ab  = vdot2(A, B);                  // d30
        P2 au  = vdot2(A, u);                  // sign = sign(-au)

        P2 q01 = mul2(aa, n1);
        P2 q12 = mul2(n1, n2);
        P2 q23 = mul2(n2, bb);
        P2 q30 = mul2(bb, aa);
        float ql, qh;
        up(q01, ql, qh); P2 r01 = pk(-rsqrtf(ql), -rsqrtf(qh));  // neg folds d01
        up(q12, ql, qh); P2 r12 = pk( rsqrtf(ql),  rsqrtf(qh));
        up(q23, ql, qh); P2 r23 = pk(-rsqrtf(ql), -rsqrtf(qh));  // neg folds d23
        up(q30, ql, qh); P2 r30 = pk( rsqrtf(ql),  rsqrtf(qh));

        P2 t0 = mul2(e01, r01);
        P2 t1 = mul2(d12, r12);
        P2 t2 = mul2(e23, r23);
        P2 t3 = mul2(ab,  r30);

        P2 omega = add2(add2(asin2(t0, ONE, NEG1, HALFPI),
                             asin2(t1, ONE, NEG1, HALFPI)),
                        add2(asin2(t2, ONE, NEG1, HALFPI),
                             asin2(t3, ONE, NEG1, HALFPI)));

        // sign(dot(c0, v2)) = sign(-au); fold 1/(2pi).
        float aul, auh; up(au, aul, auh);
        float gl = (aul < 0.0f) ? K : ((aul > 0.0f) ? -K : 0.0f);
        float gh = (auh < 0.0f) ? K : ((auh > 0.0f) ? -K : 0.0f);
        P2 res = mul2(omega, pk(gl, gh));

        float rl, rh; up(res, rl, rh);
        op[(size_t)(2 * pg)     * S_PAIRS_C] = rl;
        op[(size_t)(2 * pg + 1) * S_PAIRS_C] = rh;
    }
}

extern "C" void kernel_launch(void* const* d_in, const int* in_sizes, int n_in,
                              void* d_out, int out_size) {
    const float* xyz = (const float*)d_in[0];
    float* out = (float*)d_out;
    dim3 grid((S_PAIRS_C + BLOCK_T - 1) / BLOCK_T, N_FRAMES_C / F_TILE);
    writhe_kernel<<<grid, BLOCK_T>>>(xyz, out);
}